// round 16
// baseline (speedup 1.0000x reference)
#include <cuda_runtime.h>

// Problem constants
#define T_TOKENS 32768      // B*S
#define TM 32               // tokens per CTA
#define NTHREADS 512        // 16 warps; warp w owns codes [w*64, w*64+64)
#define AP 68               // A row pitch (floats): 64 data + pad

// Output layout (float element offsets): quantized | indices | quant | avg_probs | x
#define OFF_Q     0
#define OFF_IDX   33554432
#define OFF_QUANT 33685504
#define OFF_AVG   67239936
#define OFF_X     100794368

// smem layout (float offsets)
#define S_A     0                       // [256 d][AP]  (dup-pair, interleaved tokens)
#define S_B     (256*AP)                // 17408; 16 warps x 3 bufs x 512 floats
#define S_REDM  (S_B + 16*3*512)        // 41984; [32 tok][16 warps]
#define S_REDI  (S_REDM + 512)          // 42496
#define S_REDZ  (S_REDI + 512)          // 43008
#define S_FIXM  (S_REDZ + 512)          // 43520
#define S_FIDX  (S_FIXM + 32)           // 43552
#define S_FIXZ  (S_FIDX + 32)           // 43584
#define SM_FLOATS (S_FIXZ + 32)         // 43616 floats = 174,464 B

// 4 MB transposed codebook scratch: cbT[l][d][k]
__device__ float cbT_g[4 * 256 * 1024];

typedef unsigned long long ull;

static __device__ __forceinline__ ull pack2b(float lo, float hi) {
    ull r;
    asm("mov.b64 %0, {%1, %2};" : "=l"(r) : "f"(lo), "f"(hi));
    return r;
}
// d = a * b + d on packed f32x2 (SASS FFMA2 — 2x scalar FFMA throughput)
static __device__ __forceinline__ void ffma2(ull& d, ull a, ull b) {
    asm("fma.rn.f32x2 %0, %1, %2, %0;" : "+l"(d) : "l"(a), "l"(b));
}
static __device__ __forceinline__ float lo32(ull v) {
    return __uint_as_float((unsigned)v);
}
static __device__ __forceinline__ float hi32(ull v) {
    return __uint_as_float((unsigned)(v >> 32));
}
static __device__ __forceinline__ void cp16(float* smem_dst, const float* gsrc) {
    unsigned s = (unsigned)__cvta_generic_to_shared(smem_dst);
    asm volatile("cp.async.cg.shared.global [%0], [%1], 16;" :: "r"(s), "l"(gsrc));
}
#define CP_COMMIT() asm volatile("cp.async.commit_group;")
#define CP_WAIT0()  asm volatile("cp.async.wait_group 0;")
#define CP_WAIT1()  asm volatile("cp.async.wait_group 1;")
#define CP_WAIT2()  asm volatile("cp.async.wait_group 2;")

// ---------- pre-pass: codebook transpose cb[l][k][d] -> cbT[l][d][k] ----------
__global__ void transpose_cb(const float* __restrict__ cb)
{
    __shared__ float tile[32][33];
    const int l  = blockIdx.z;
    const int db = blockIdx.x * 32;     // d block
    const int kb = blockIdx.y * 32;     // k block
    const float* src = cb + l * 262144;
    float* dst = cbT_g + l * 262144;
    const int tx = threadIdx.x, ty0 = threadIdx.y;   // block (32, 8)
    #pragma unroll
    for (int i = 0; i < 4; ++i) {
        int k = kb + ty0 + i * 8;
        tile[ty0 + i * 8][tx] = src[k * 256 + db + tx];
    }
    __syncthreads();
    #pragma unroll
    for (int i = 0; i < 4; ++i) {
        int d = db + ty0 + i * 8;
        dst[d * 1024 + kb + tx] = tile[tx][ty0 + i * 8];
    }
}

// ---------- main kernel ----------
__global__ __launch_bounds__(NTHREADS, 1)
void ahq_kernel(const float* __restrict__ x,
                const float* __restrict__ cb,
                const float* __restrict__ temp,
                float* __restrict__ out)
{
    extern __shared__ float sm[];
    float* redM = sm + S_REDM;
    int*   redI = (int*)(sm + S_REDI);
    float* redZ = sm + S_REDZ;
    float* fixM = sm + S_FIXM;
    int*   fidx = (int*)(sm + S_FIDX);
    float* fixZ = sm + S_FIXZ;

    const int t      = threadIdx.x;
    const int w      = t >> 5;           // warp -> code block [w*64, w*64+64)
    const int lane   = t & 31;
    const int tp     = lane >> 4;        // token half (16 tokens each)
    const int cg     = lane & 15;        // code group (4 codes)
    const int token0 = blockIdx.x * TM;
    const float inv_tau = 1.0f / fmaxf(temp[0], 0.04f);

    float* Bw = sm + S_B + w * 1536;     // warp-private 3 x 512-float buffers

    ull acc2[32];   // 16 tokens x 4 codes: acc2[j*4 + {0,1}] = tok 2j, {2,3} = tok 2j+1

    for (int l = 0; l < 4; ++l) {
        #pragma unroll
        for (int i = 0; i < 32; ++i) acc2[i] = 0ULL;

        // warp-private async copy of one 8d x 64-code chunk (2 KB)
        auto cpB = [&](int buf, int chunk) {
            const float* srcb = cbT_g + (l << 18) + (chunk << 13) + (w << 6);
            float* dst = Bw + buf * 512;
            #pragma unroll
            for (int p = 0; p < 4; ++p) {
                int idx4 = lane + (p << 5);            // float4 index in chunk
                int dl   = idx4 >> 4;                  // d within chunk
                int col  = (idx4 & 15) << 2;           // code offset
                cp16(dst + (idx4 << 2), srcb + (dl << 10) + col);
            }
        };

        // prefetch chunks 0,1 (overlaps the A-load section below)
        cpB(0, 0); CP_COMMIT();
        cpB(1, 1); CP_COMMIT();

        // ---- A load: x slice -> smem (1/tau-scaled, dup-pair, interleaved) ----
        // token order per d-row: pos (j*2+tp)*4 + e*2 holds token tp*16+2j+e dup
        {
            int tok = t >> 4;            // 0..31
            int dg  = t & 15;            // 0..15 (16 d per thread as 4 float4)
            const float4* xs = (const float4*)(x + ((token0 + tok) << 10) + (l << 8));
            float4* xd = (float4*)(out + OFF_X + ((token0 + tok) << 10) + (l << 8));
            int ttp = tok >> 4, r = tok & 15, j = r >> 1, e = r & 1;
            int colb = ((j << 1) + ttp) * 4 + (e << 1);
            #pragma unroll
            for (int p = 0; p < 4; ++p) {
                float4 a = xs[(dg << 2) + p];
                xd[(dg << 2) + p] = a;                 // fused x copy
                int d = (dg << 4) + (p << 2);
                float s0 = a.x * inv_tau, s1 = a.y * inv_tau;
                float s2 = a.z * inv_tau, s3 = a.w * inv_tau;
                *(ull*)(sm + S_A + (d + 0) * AP + colb) = pack2b(s0, s0);
                *(ull*)(sm + S_A + (d + 1) * AP + colb) = pack2b(s1, s1);
                *(ull*)(sm + S_A + (d + 2) * AP + colb) = pack2b(s2, s2);
                *(ull*)(sm + S_A + (d + 3) * AP + colb) = pack2b(s3, s3);
            }
        }
        __syncthreads();   // A visible to all warps (the ONLY mainloop-wide barrier)

        // ---- barrier-free mainloop: 32 chunks of 8 d, warp-private pipeline ----
        #pragma unroll 1
        for (int c = 0; c < 32; ++c) {
            if (c + 2 < 32) { cpB((c + 2) % 3, c + 2); CP_COMMIT(); CP_WAIT2(); }
            else if (c + 1 < 32) { CP_WAIT1(); }
            else { CP_WAIT0(); }
            __syncwarp();
            const float* Bb = Bw + (c % 3) * 512 + (cg << 2);
            const int d0 = c << 3;
            #pragma unroll
            for (int d = 0; d < 8; ++d) {
                ulonglong2 b = *(const ulonglong2*)(Bb + (d << 6));  // codes cg*4..+3
                const float* Ad = sm + S_A + (d0 + d) * AP + (tp << 2);
                #pragma unroll
                for (int j = 0; j < 8; ++j) {
                    ulonglong2 av = *(const ulonglong2*)(Ad + (j << 3)); // tok 2j,2j+1
                    ffma2(acc2[(j << 2) + 0], av.x, b.x);
                    ffma2(acc2[(j << 2) + 1], av.x, b.y);
                    ffma2(acc2[(j << 2) + 2], av.y, b.x);
                    ffma2(acc2[(j << 2) + 3], av.y, b.y);
                }
            }
        }

        // ================= epilogue for layer l =================
        const int cb0 = (w << 6) + (cg << 2);
        // 1) per-token argmax over this warp's 64 codes (min-index tie-break)
        #pragma unroll
        for (int tt = 0; tt < 16; ++tt) {
            int base = ((tt >> 1) << 2) + ((tt & 1) << 1);
            ull v0 = acc2[base], v1 = acc2[base + 1];
            float m = lo32(v0); int mi = cb0;
            float h0 = hi32(v0);
            if (h0 > m) { m = h0; mi = cb0 + 1; }
            float l1 = lo32(v1);
            if (l1 > m) { m = l1; mi = cb0 + 2; }
            float h1 = hi32(v1);
            if (h1 > m) { m = h1; mi = cb0 + 3; }
            #pragma unroll
            for (int off = 8; off > 0; off >>= 1) {
                float om = __shfl_down_sync(0xffffffffu, m, off, 16);
                int   oi = __shfl_down_sync(0xffffffffu, mi, off, 16);
                if (om > m || (om == m && oi < mi)) { m = om; mi = oi; }
            }
            if (cg == 0) {
                int gtok = (tp << 4) + tt;
                redM[gtok * 16 + w] = m;
                redI[gtok * 16 + w] = mi;
            }
        }
        __syncthreads();
        // 2) cross-warp argmax (ascending w => strict > keeps min code index)
        if (t < 32) {
            float m = redM[t * 16]; int mi = redI[t * 16];
            #pragma unroll
            for (int g = 1; g < 16; ++g) {
                float om = redM[t * 16 + g];
                if (om > m) { m = om; mi = redI[t * 16 + g]; }
            }
            fixM[t] = m; fidx[t] = mi;
            out[OFF_IDX + (token0 + t) * 4 + l] = (float)mi;
        }
        __syncthreads();
        // 3) exp + partial Z (overwrite acc2 with exp values)
        #pragma unroll
        for (int tt = 0; tt < 16; ++tt) {
            int gtok = (tp << 4) + tt;
            float Mv = fixM[gtok];
            int base = ((tt >> 1) << 2) + ((tt & 1) << 1);
            float e0 = __expf(lo32(acc2[base])     - Mv);
            float e1 = __expf(hi32(acc2[base])     - Mv);
            float e2 = __expf(lo32(acc2[base + 1]) - Mv);
            float e3 = __expf(hi32(acc2[base + 1]) - Mv);
            acc2[base]     = pack2b(e0, e1);
            acc2[base + 1] = pack2b(e2, e3);
            float s = (e0 + e1) + (e2 + e3);
            #pragma unroll
            for (int off = 8; off > 0; off >>= 1)
                s += __shfl_down_sync(0xffffffffu, s, off, 16);
            if (cg == 0) redZ[gtok * 16 + w] = s;
        }
        __syncthreads();
        if (t < 32) {
            float s = 0.0f;
            #pragma unroll
            for (int g = 0; g < 16; ++g) s += redZ[t * 16 + g];
            fixZ[t] = 0.25f / s;          // softmax norm * 1/L
        }
        __syncthreads();
        // 4) avg-probs accumulate via gmem RMW (L2-resident; per-lane cell
        //    ownership is layer-invariant -> race-free)
        #pragma unroll
        for (int tt = 0; tt < 16; ++tt) {
            int gtok = (tp << 4) + tt;
            int token = token0 + gtok;
            ull iz = pack2b(fixZ[gtok], fixZ[gtok]);
            int base = ((tt >> 1) << 2) + ((tt & 1) << 1);
            ull* pp = (ull*)(out + OFF_AVG + (token << 10) + cb0);
            ulonglong2 pv;
            if (l == 0) { pv.x = 0ULL; pv.y = 0ULL; }
            else        { pv = *(ulonglong2*)pp; }
            ffma2(pv.x, acc2[base],     iz);
            ffma2(pv.y, acc2[base + 1], iz);
            *(ulonglong2*)pp = pv;
        }
        // 5) hard_q gather: 16 threads per token (fidx stable since step 2)
        {
            int tokg   = t >> 4;
            int lane16 = t & 15;
            int mi = fidx[tokg];
            const float4* crow = (const float4*)(cb + (((l << 10) + mi) << 8));
            int qbase = (token0 + tokg) * 256 + (l << 6) + lane16;   // float4 units
            #pragma unroll
            for (int p = 0; p < 4; ++p) {
                float4 q = crow[(p << 4) + lane16];
                ((float4*)out)[(OFF_Q     >> 2) + qbase + (p << 4)] = q;   // quantized
                ((float4*)out)[(OFF_QUANT >> 2) + qbase + (p << 4)] = q;   // quant
            }
        }
        // next layer: A-store happens after this epilogue's barriers; red/fidx
        // rewritten only after next layer's own barriers -> ordering safe
    }
}

extern "C" void kernel_launch(void* const* d_in, const int* in_sizes, int n_in,
                              void* d_out, int out_size)
{
    const float* x    = (const float*)d_in[0];
    const float* cb   = (const float*)d_in[1];
    const float* temp = (const float*)d_in[2];
    float* out = (float*)d_out;
    (void)in_sizes; (void)n_in; (void)out_size;

    // pre-pass: transpose codebook into cbT_g (d-major)
    transpose_cb<<<dim3(8, 32, 4), dim3(32, 8)>>>(cb);

    size_t smem = SM_FLOATS * sizeof(float);   // ~174.5 KB (< 227 KB sm_103a cap)
    cudaFuncSetAttribute(ahq_kernel, cudaFuncAttributeMaxDynamicSharedMemorySize, (int)smem);
    ahq_kernel<<<T_TOKENS / TM, NTHREADS, smem>>>(x, cb, temp, out);
}